// round 4
// baseline (speedup 1.0000x reference)
#include <cuda_runtime.h>

// WorkingYOLOLoss on GB300 (sm_103a) — one thread per (target, channel)
// pred:    d_in[0]  (64, 8, 256, 256) float32
// targets: d_in[1]  (64, 200, 5)      float32  [cls_id, x, y, w, h]
// out:     4 float32  [total, bbox_sum, obj_sum, cls_sum]

#define B_DIM 64
#define N_TGT 200
#define NTOT (B_DIM * N_TGT)       // 12800 targets
#define NTHREADS_TOT (NTOT * 8)    // 102400 threads (one per gathered scalar)
#define HW 65536                   // 256*256
#define BBOX_W 0.05f
#define OBJ_W  1.0f
#define CLS_W  0.5f

#define THREADS 256
#define BLOCKS  (NTHREADS_TOT / THREADS)   // 400

// Device scratch: [bbox, obj, cls] accumulators + completion counter.
// Zero-initialized at load; the LAST block of every launch resets them,
// so every graph replay starts clean.
__device__ float g_acc[3] = {0.f, 0.f, 0.f};
__device__ unsigned int g_done = 0;

__device__ __forceinline__ float softplus_f(float x) {
    return fmaxf(x, 0.0f) + log1pf(expf(-fabsf(x)));
}

__global__ void __launch_bounds__(THREADS) yolo_loss_kernel(
    const float* __restrict__ pred,
    const float* __restrict__ targets,
    float* __restrict__ out)
{
    int t   = blockIdx.x * THREADS + threadIdx.x;  // 0..102399 (exact grid)
    int tgt = t >> 3;                              // target index
    int ch  = t & 7;                               // channel 0..7

    // All 8 lanes of a group read the same 5 floats — L1 broadcast.
    const float* tr = targets + (size_t)tgt * 5;
    float cid = tr[0];
    float c0 = tr[1], c1 = tr[2], c2 = tr[3], c3 = tr[4];

    bool valid = (cid >= 0.0f) && ((c0 + c1 + c2 + c3) > 0.0f);
    int xp = (int)(c0 * 256.0f);   // truncation, matches astype(int32)
    int yp = (int)(c1 * 256.0f);
    bool inb = (xp >= 0) && (xp < 256) && (yp >= 0) && (yp < 256);

    float bbox = 0.0f, obj = 0.0f, cls = 0.0f;

    if (valid && inb) {
        int b = tgt / N_TGT;
        float p = pred[((size_t)b << 19) + ((size_t)ch << 16)
                       + ((size_t)yp << 8) + xp];

        if (ch < 4) {
            float c = (ch == 0) ? c0 : (ch == 1) ? c1 : (ch == 2) ? c2 : c3;
            float d = p - c;
            bbox = 0.25f * d * d;
        } else if (ch == 4) {
            obj = softplus_f(p) - p;               // BCE(z=1)
        } else {
            int ci = (int)cid;                     // cid >= 0 here
            float hit = ((ch - 5) == ci) ? p : 0.0f;
            cls = (softplus_f(p) - hit) * (1.0f / 3.0f);
        }
    }

    // ---- warp reduce (3 components, 32 lanes = 4 targets) ----
    #pragma unroll
    for (int off = 16; off > 0; off >>= 1) {
        bbox += __shfl_down_sync(0xFFFFFFFFu, bbox, off);
        obj  += __shfl_down_sync(0xFFFFFFFFu, obj,  off);
        cls  += __shfl_down_sync(0xFFFFFFFFu, cls,  off);
    }

    // ---- block reduce across 8 warps ----
    __shared__ float s_red[3][8];
    int lane = threadIdx.x & 31;
    int wid  = threadIdx.x >> 5;
    if (lane == 0) {
        s_red[0][wid] = bbox;
        s_red[1][wid] = obj;
        s_red[2][wid] = cls;
    }
    __syncthreads();

    if (threadIdx.x < 32) {
        bbox = (lane < 8) ? s_red[0][lane] : 0.0f;
        obj  = (lane < 8) ? s_red[1][lane] : 0.0f;
        cls  = (lane < 8) ? s_red[2][lane] : 0.0f;
        #pragma unroll
        for (int off = 4; off > 0; off >>= 1) {
            bbox += __shfl_down_sync(0xFFFFFFFFu, bbox, off);
            obj  += __shfl_down_sync(0xFFFFFFFFu, obj,  off);
            cls  += __shfl_down_sync(0xFFFFFFFFu, cls,  off);
        }

        if (lane == 0) {
            atomicAdd(&g_acc[0], bbox);
            atomicAdd(&g_acc[1], obj);
            atomicAdd(&g_acc[2], cls);
            __threadfence();
            unsigned int ticket = atomicAdd(&g_done, 1u);
            if (ticket == (unsigned int)(gridDim.x - 1)) {
                // last block: read totals, finalize, reset for next replay
                float fb = g_acc[0], fo = g_acc[1], fc = g_acc[2];
                out[0] = BBOX_W * fb + OBJ_W * fo + CLS_W * fc;
                out[1] = fb;
                out[2] = fo;
                out[3] = fc;
                g_acc[0] = 0.0f;
                g_acc[1] = 0.0f;
                g_acc[2] = 0.0f;
                g_done = 0u;
                __threadfence();
            }
        }
    }
}

extern "C" void kernel_launch(void* const* d_in, const int* in_sizes, int n_in,
                              void* d_out, int out_size) {
    const float* pred    = (const float*)d_in[0];
    const float* targets = (const float*)d_in[1];
    float* out = (float*)d_out;

    yolo_loss_kernel<<<BLOCKS, THREADS>>>(pred, targets, out);
}